// round 13
// baseline (speedup 1.0000x reference)
#include <cuda_runtime.h>

// LengthRegulator, two-kernel form, BOTH kernels PDL-overlapped:
//   out[b, f, :] = xs[b, searchsorted(cumsum(ds[b]), f, right), :]
//   (0 if f >= total); all-zero ds rows treated as all-ones.
// B=32, T=512, D=384, MAX_FRAMES=2048.

#define BB 32
#define TT 512
#define DD 384
#define MF 2048
#define D4 (DD / 4)        // 96 float4 per frame
#define NFR (BB * MF)      // 65536 global frames
#define GTHR 192           // 2 x 96 lanes
#define FPBLK 8            // frames per gather block
#define GBLKS (NFR / FPBLK)// 8192 blocks

// Frame -> source-token index map; -1 means padding (write zeros).
__device__ int g_idx[NFR];

// ---------------------------------------------------------------------------
// Kernel A: per-batch inclusive scan + scatter int32 map. One block per
// batch, 128 threads, 4 tokens each. ALL g_idx writes happen after the PDL
// gate (WAR hazard vs the previous replay's gather reading g_idx); all loads
// and the scan computation happen before it, overlapping the prior kernel.
// ds dtype (int32 vs int64) detected at runtime: durations are in [0,4], so
// an int64 buffer has every odd int32 word == 0. P(false positive) = 0.2^128.
// ---------------------------------------------------------------------------
__global__ void __launch_bounds__(128) lr_scan_kernel(const int* __restrict__ ds32) {
    const int b    = blockIdx.x;
    const int tid  = threadIdx.x;
    const int lane = tid & 31;
    const int wid  = tid >> 5;                 // 4 warps

    __shared__ int s_warp[4];
    __shared__ int s_off[5];
    __shared__ int s_bad;

    if (tid == 0) s_bad = 0;
    const int samp = ds32[(tid * 256 + 1) & 16383];  // odd int32 words
    __syncthreads();
    if (samp != 0) atomicOr(&s_bad, 1);
    __syncthreads();
    const bool is64 = (s_bad == 0);

    // --- load 4 durations per thread (tokens 4*tid .. 4*tid+3) ---
    int d0, d1, d2, d3;
    if (is64) {
        longlong2 p = ((const longlong2*)ds32)[b * (TT / 2) + 2 * tid];
        longlong2 q = ((const longlong2*)ds32)[b * (TT / 2) + 2 * tid + 1];
        d0 = (int)p.x; d1 = (int)p.y; d2 = (int)q.x; d3 = (int)q.y;
    } else {
        int4 p = ((const int4*)ds32)[b * (TT / 4) + tid];
        d0 = p.x; d1 = p.y; d2 = p.z; d3 = p.w;
    }

    // --- hierarchical inclusive scan over 512 (4 per thread) ---
    const int sum4 = d0 + d1 + d2 + d3;
    int incl = sum4;
#pragma unroll
    for (int off = 1; off < 32; off <<= 1) {
        int n = __shfl_up_sync(0xFFFFFFFFu, incl, off);
        if (lane >= off) incl += n;
    }
    if (lane == 31) s_warp[wid] = incl;
    __syncthreads();
    if (wid == 0) {
        int w = (lane < 4) ? s_warp[lane] : 0;
#pragma unroll
        for (int off = 1; off < 4; off <<= 1) {
            int n = __shfl_up_sync(0xFFFFFFFFu, w, off);
            if (lane >= off) w += n;
        }
        if (lane < 4) s_off[lane + 1] = w;
        if (lane == 0) s_off[0] = 0;
    }
    __syncthreads();

    int excl = incl - sum4 + s_off[wid];       // exclusive prefix at token 4*tid
    const int total = s_off[4];

    // ---- PDL gate: previous kernel (prior replay's gather) must be done
    //      before we overwrite g_idx. Everything above overlapped with it. ----
    cudaGridDependencySynchronize();

    // init this batch's g_idx to -1 (512 int4 stores across 128 threads)
#pragma unroll
    for (int k = 0; k < 4; k++)
        ((int4*)g_idx)[b * (MF / 4) + tid + k * 128] = make_int4(-1, -1, -1, -1);
    __syncthreads();   // order init before scatter within the block

    if (total == 0) {
        // all-zero row => durations all 1 => identity map for f < T
#pragma unroll
        for (int k = 0; k < 4; k++)
            g_idx[b * MF + 4 * tid + k] = 4 * tid + k;
    } else {
        int dd[4] = {d0, d1, d2, d3};
#pragma unroll
        for (int q = 0; q < 4; q++) {
            const int en = excl + dd[q];
            for (int f = excl; f < en; f++)
                g_idx[b * MF + f] = 4 * tid + q;
            excl = en;
        }
    }
}

// ---------------------------------------------------------------------------
// Kernel B: bandwidth mover (write-bandwidth floor; unchanged structure).
// Block = 192 threads (2 x 96 lanes), 8 frames per block. Fixed column per
// thread; per frame: warp-uniform idx load, clamped unconditional LDG.128,
// select-zero on pad, streaming STG.128. Gated on the scan via PDL.
// ---------------------------------------------------------------------------
__global__ void __launch_bounds__(GTHR)
lr_gather_kernel(const float4* __restrict__ xs, float4* __restrict__ out) {
    const int tid = threadIdx.x;
    const int c   = tid % D4;                  // fixed column (0..95)
    const int sub = tid / D4;                  // 0 or 1
    const int gf0 = blockIdx.x * FPBLK + sub;  // global frame, step 2

    // Wait for the scan kernel's writes to be visible (PDL gate).
    cudaGridDependencySynchronize();

    int idx[4];
    const float4* src[4];
#pragma unroll
    for (int k = 0; k < 4; k++) {
        const int gf = gf0 + 2 * k;
        const int b  = gf >> 11;               // gf / MF
        const int raw = g_idx[gf];             // warp-uniform broadcast load
        idx[k] = raw;
        const int safe = raw < 0 ? 0 : raw;    // clamp: always in-bounds
        src[k] = xs + (size_t)(b * TT + safe) * D4 + c;
    }

    float4 v[4];
#pragma unroll
    for (int k = 0; k < 4; k++)
        v[k] = __ldg(src[k]);                  // unconditional LDG.128

#pragma unroll
    for (int k = 0; k < 4; k++) {
        const bool pad = idx[k] < 0;
        v[k].x = pad ? 0.f : v[k].x;
        v[k].y = pad ? 0.f : v[k].y;
        v[k].z = pad ? 0.f : v[k].z;
        v[k].w = pad ? 0.f : v[k].w;
        __stcs(&out[(size_t)(gf0 + 2 * k) * D4 + c], v[k]);
    }
}

// ---------------------------------------------------------------------------
extern "C" void kernel_launch(void* const* d_in, const int* in_sizes, int n_in,
                              void* d_out, int out_size) {
    // Select pointers by element count (xs: 6,291,456 floats; ds: 16,384).
    const float* xs;
    const int* ds;
    if (in_sizes[0] > in_sizes[1]) {
        xs = (const float*)d_in[0];  ds = (const int*)d_in[1];
    } else {
        xs = (const float*)d_in[1];  ds = (const int*)d_in[0];
    }
    float4* out = (float4*)d_out;

    cudaLaunchAttribute attrs[1];
    attrs[0].id = cudaLaunchAttributeProgrammaticStreamSerialization;
    attrs[0].val.programmaticStreamSerializationAllowed = 1;

    // Scan with PDL: overlaps with the previous graph node (prior replay's
    // gather); gates internally before writing g_idx.
    cudaLaunchConfig_t scfg = {};
    scfg.gridDim  = dim3(BB, 1, 1);
    scfg.blockDim = dim3(128, 1, 1);
    scfg.dynamicSmemBytes = 0;
    scfg.stream = 0;
    scfg.attrs = attrs;
    scfg.numAttrs = 1;
    cudaLaunchKernelEx(&scfg, lr_scan_kernel, ds);

    // Gather with PDL: overlaps launch/ramp with the scan; gates internally
    // before reading g_idx.
    cudaLaunchConfig_t gcfg = {};
    gcfg.gridDim  = dim3(GBLKS, 1, 1);
    gcfg.blockDim = dim3(GTHR, 1, 1);
    gcfg.dynamicSmemBytes = 0;
    gcfg.stream = 0;
    gcfg.attrs = attrs;
    gcfg.numAttrs = 1;
    cudaLaunchKernelEx(&gcfg, lr_gather_kernel, (const float4*)xs, out);
}